// round 2
// baseline (speedup 1.0000x reference)
#include <cuda_runtime.h>

// Detail loss, simplified:
//   D = sum_c (infer - ref)   (per image plane)
//   out = (sum|D[w+1]-D[w-1]| + sum|D[h+1]-D[h-1]|) * 0.25 / (98*258*256)
// (zero padding; both conv means share the identical denominator since H==W,
//  and the 3 duplicated output channels cancel).

#define NIMG 98          // 2*7*7
#define IMG_H 256
#define IMG_W 256
#define ROWS 64          // rows of D per block
#define STRIPS (IMG_H / ROWS)          // 4
#define NBLOCKS (NIMG * STRIPS)        // 392  -> single wave at occ 3 on 152 SMs
#define PLANE (IMG_H * IMG_W)          // 65536
#define SMEM_BYTES ((ROWS + 2) * IMG_W * 4)   // 67584

__device__ float        g_block_sums[NBLOCKS];
__device__ unsigned int g_counter;            // zero-init; reset by last block

__global__ void __launch_bounds__(256, 3)
detail_fused(const float* __restrict__ infer, const float* __restrict__ ref,
             float* __restrict__ out) {
    extern __shared__ float Dsh[];   // (ROWS+2) x IMG_W

    const int blk   = blockIdx.x;
    const int n     = blk / STRIPS;
    const int strip = blk % STRIPS;
    const int r0    = strip * ROWS;
    const int tid   = threadIdx.x;

    const float* pi = infer + (size_t)n * 3 * PLANE;
    const float* pr = ref   + (size_t)n * 3 * PLANE;

    // ---- Load (ROWS+2) rows of D into shared; zero rows outside the image ----
    const int V4 = IMG_W / 4;  // 64 float4 per row
    #pragma unroll 1
    for (int idx = tid; idx < (ROWS + 2) * V4; idx += 256) {
        const int row = idx >> 6;          // /64
        const int c4  = idx & 63;
        const int gh  = r0 - 1 + row;
        float4 d = make_float4(0.f, 0.f, 0.f, 0.f);
        if (gh >= 0 && gh < IMG_H) {
            const size_t off = (size_t)gh * IMG_W + c4 * 4;
            #pragma unroll
            for (int c = 0; c < 3; c++) {
                const float4 a = __ldcs((const float4*)(pi + (size_t)c * PLANE + off));
                const float4 b = __ldcs((const float4*)(pr + (size_t)c * PLANE + off));
                d.x += a.x - b.x;
                d.y += a.y - b.y;
                d.z += a.z - b.z;
                d.w += a.w - b.w;
            }
        }
        *(float4*)(Dsh + row * IMG_W + c4 * 4) = d;
    }
    __syncthreads();

    // ---- Stencil walk: thread owns column w, rolls center values in regs ----
    const int w = tid;
    float sum = 0.f;
    float cm = Dsh[w];               // D[r0-1][w]
    float cc = Dsh[IMG_W + w];       // D[r0  ][w]
    #pragma unroll 8
    for (int h = 0; h < ROWS; h++) {
        const float* rowc = Dsh + (h + 1) * IMG_W;   // row r0+h
        const float* rowp = rowc + IMG_W;            // row r0+h+1
        const float cp = rowp[w];
        const float l  = (w > 0)         ? rowc[w - 1] : 0.f;
        const float r  = (w < IMG_W - 1) ? rowc[w + 1] : 0.f;
        sum += fabsf(r - l);         // horizontal gradient (0.5 folded into scale)
        sum += fabsf(cp - cm);       // vertical gradient
        cm = cc;
        cc = cp;
    }

    // ---- Block reduction ----
    #pragma unroll
    for (int off = 16; off > 0; off >>= 1)
        sum += __shfl_down_sync(0xffffffffu, sum, off);
    __shared__ float wsum[8];
    __shared__ bool  is_last;
    if ((tid & 31) == 0) wsum[tid >> 5] = sum;
    __syncthreads();
    if (tid == 0) {
        float s = 0.f;
        #pragma unroll
        for (int i = 0; i < 8; i++) s += wsum[i];
        g_block_sums[blk] = s;
        __threadfence();
        unsigned int old = atomicAdd(&g_counter, 1u);
        is_last = (old == NBLOCKS - 1);
    }
    __syncthreads();

    // ---- Last block performs the final reduction (deterministic order) ----
    if (is_last) {
        float s = 0.f;
        for (int i = tid; i < NBLOCKS; i += 256) s += g_block_sums[i];
        #pragma unroll
        for (int off = 16; off > 0; off >>= 1)
            s += __shfl_down_sync(0xffffffffu, s, off);
        if ((tid & 31) == 0) wsum[tid >> 5] = s;
        __syncthreads();
        if (tid == 0) {
            float t = 0.f;
            #pragma unroll
            for (int i = 0; i < 8; i++) t += wsum[i];
            // 0.5 (gradient coeff) * 0.5 (avg of two losses) / (98*258*256)
            out[0] = t * (0.25f / 6472704.0f);
            g_counter = 0;   // reset so every graph replay behaves identically
        }
    }
}

extern "C" void kernel_launch(void* const* d_in, const int* in_sizes, int n_in,
                              void* d_out, int out_size) {
    const float* infer = (const float*)d_in[0];
    const float* ref   = (const float*)d_in[1];
    float* out = (float*)d_out;

    cudaFuncSetAttribute(detail_fused,
                         cudaFuncAttributeMaxDynamicSharedMemorySize, SMEM_BYTES);
    detail_fused<<<NBLOCKS, 256, SMEM_BYTES>>>(infer, ref, out);
}